// round 1
// baseline (speedup 1.0000x reference)
#include <cuda_runtime.h>

// Problem constants
#define B_   8
#define N_   1024
#define D_   768
#define H_   12
#define HD_  64
#define ROWS (B_ * N_)      // 8192
#define D3_  (3 * D_)       // 2304
#define SCALE_ 0.125f       // 64^-0.5

// Scratch (alloc-free rule: device globals)
__device__ __align__(16) float g_Q[B_ * H_ * N_ * HD_];
__device__ __align__(16) float g_K[B_ * H_ * N_ * HD_];
__device__ __align__(16) float g_V[B_ * H_ * N_ * HD_];
__device__ __align__(16) float g_attn[ROWS * D_];

// ---------------------------------------------------------------------------
// Tiled SGEMM: C[8192 x NCOLS] = A[8192 x 768] * B[768 x NCOLS]
// BM=BN=128, BK=8, 256 threads, 8x8 per-thread tile.
// MODE 0: qkv — gate by aux[row], scatter into g_Q/g_K/g_V ([B,H,N,hd] layout)
// MODE 1: proj — A is g_attn, add bias aux[col], write C.
// ---------------------------------------------------------------------------
template <int LDB, int MODE>
__global__ __launch_bounds__(256, 2) void gemm128(
    const float* __restrict__ A, const float* __restrict__ Bm,
    const float* __restrict__ aux, float* __restrict__ C)
{
  __shared__ float As[8][128];   // transposed A tile: As[k][m]
  __shared__ float Bs[8][128];

  const int tid = threadIdx.x;
  const float* Ap = (MODE == 0 ? A : (const float*)g_attn)
                    + (size_t)blockIdx.y * 128 * D_;
  const float* Bp = Bm + blockIdx.x * 128;

  const int aRow = tid >> 1;           // 0..127
  const int aCol = (tid & 1) << 2;     // 0 or 4
  const int bRow = tid >> 5;           // 0..7
  const int bCol = (tid & 31) << 2;    // 0..124
  const int tr   = (tid >> 4) << 3;    // output row base
  const int tc   = (tid & 15) << 3;    // output col base

  float acc[8][8];
#pragma unroll
  for (int i = 0; i < 8; i++)
#pragma unroll
    for (int j = 0; j < 8; j++) acc[i][j] = 0.f;

  for (int k0 = 0; k0 < D_; k0 += 8) {
    float4 av = *reinterpret_cast<const float4*>(Ap + (size_t)aRow * D_ + k0 + aCol);
    As[aCol + 0][aRow] = av.x;
    As[aCol + 1][aRow] = av.y;
    As[aCol + 2][aRow] = av.z;
    As[aCol + 3][aRow] = av.w;
    *reinterpret_cast<float4*>(&Bs[bRow][bCol]) =
        *reinterpret_cast<const float4*>(Bp + (size_t)(k0 + bRow) * LDB + bCol);
    __syncthreads();

#pragma unroll
    for (int k = 0; k < 8; k++) {
      float ar[8], br[8];
      *reinterpret_cast<float4*>(ar)     = *reinterpret_cast<float4*>(&As[k][tr]);
      *reinterpret_cast<float4*>(ar + 4) = *reinterpret_cast<float4*>(&As[k][tr + 4]);
      *reinterpret_cast<float4*>(br)     = *reinterpret_cast<float4*>(&Bs[k][tc]);
      *reinterpret_cast<float4*>(br + 4) = *reinterpret_cast<float4*>(&Bs[k][tc + 4]);
#pragma unroll
      for (int i = 0; i < 8; i++)
#pragma unroll
        for (int j = 0; j < 8; j++) acc[i][j] += ar[i] * br[j];
    }
    __syncthreads();
  }

  if (MODE == 0) {
#pragma unroll
    for (int i = 0; i < 8; i++) {
      int row = blockIdx.y * 128 + tr + i;
      float g = aux[row];                       // per-token gate
      int b = row >> 10, n = row & 1023;
#pragma unroll
      for (int j = 0; j < 8; j++) {
        int col = blockIdx.x * 128 + tc + j;
        int which = col / D_;
        int dd = col - which * D_;
        int h = dd >> 6, hd = dd & 63;
        float* dst = (which == 0) ? g_Q : ((which == 1) ? g_K : g_V);
        dst[(size_t)(((b * H_ + h) << 10) + n) * HD_ + hd] = acc[i][j] * g;
      }
    }
  } else {
#pragma unroll
    for (int i = 0; i < 8; i++) {
      int row = blockIdx.y * 128 + tr + i;
#pragma unroll
      for (int j = 0; j < 8; j++) {
        int col = blockIdx.x * 128 + tc + j;
        C[(size_t)row * D_ + col] = acc[i][j] + aux[col];
      }
    }
  }
}

// ---------------------------------------------------------------------------
// Attention: per (b,h) head, 32 query rows per block, full scores in SMEM.
// S is stored TRANSPOSED (St[key][query], stride 36) so every inner-loop SMEM
// access is either a lane-broadcast scalar or a conflict-free float4.
// ---------------------------------------------------------------------------
#define ST_STRIDE 36
#define KV_STRIDE 68
#define SM_QT (N_ * ST_STRIDE)           // 36864 floats
#define SM_KV (SM_QT + 64 * ST_STRIDE)   // + 2304 = 39168
#define SM_RS (SM_KV + 64 * KV_STRIDE)   // + 4352 = 43520
#define SM_FLOATS (SM_RS + 32)           // 43552 floats = 174208 B

__global__ __launch_bounds__(256, 1) void attn_kernel()
{
  extern __shared__ __align__(16) float sm[];
  float* St = sm;            // [1024][36]  St[m][r] = S[r][m]
  float* Qt = sm + SM_QT;    // [64][36]    Qt[d][r]  (pre-scaled)
  float* KV = sm + SM_KV;    // [64][68]    K or V tile (natural layout)
  float* RS = sm + SM_RS;    // [32]        1/rowsum

  const int tid = threadIdx.x;
  const int bh  = blockIdx.y;          // 0..95
  const int q0  = blockIdx.x << 5;     // query tile start
  const float* Qg = g_Q + ((size_t)bh * N_ + q0) * HD_;
  const float* Kg = g_K + (size_t)bh * N_ * HD_;
  const float* Vg = g_V + (size_t)bh * N_ * HD_;

  // --- load + transpose Q (fold in softmax scale) ---
  {
    int r  = tid >> 4;            // 0..15
    int d4 = (tid & 15) << 2;     // 0..60
#pragma unroll
    for (int rr = r; rr < 32; rr += 16) {
      float4 q = *reinterpret_cast<const float4*>(Qg + (size_t)rr * HD_ + d4);
      Qt[(d4 + 0) * ST_STRIDE + rr] = q.x * SCALE_;
      Qt[(d4 + 1) * ST_STRIDE + rr] = q.y * SCALE_;
      Qt[(d4 + 2) * ST_STRIDE + rr] = q.z * SCALE_;
      Qt[(d4 + 3) * ST_STRIDE + rr] = q.w * SCALE_;
    }
  }

  const int ld_c  = tid >> 4;           // tile-load row
  const int ld_d4 = (tid & 15) << 2;    // tile-load col (float4)
  const int cgrp  = tid >> 3;           // 0..31  -> 2 key rows
  const int rg4   = (tid & 7) << 2;     // 0..28  -> 4 query cols

  // --- phase 1: St[kt..kt+63][0..31] = K_tile . Qt ---
  for (int kt = 0; kt < N_; kt += 64) {
    __syncthreads();
#pragma unroll
    for (int cc = ld_c; cc < 64; cc += 16)
      *reinterpret_cast<float4*>(&KV[cc * KV_STRIDE + ld_d4]) =
          *reinterpret_cast<const float4*>(Kg + (size_t)(kt + cc) * HD_ + ld_d4);
    __syncthreads();

    float s0[4] = {0, 0, 0, 0}, s1[4] = {0, 0, 0, 0};
    const float* k0p = &KV[(cgrp * 2 + 0) * KV_STRIDE];
    const float* k1p = &KV[(cgrp * 2 + 1) * KV_STRIDE];
#pragma unroll 8
    for (int d = 0; d < 64; d++) {
      float kk0 = k0p[d], kk1 = k1p[d];
      float4 qv = *reinterpret_cast<float4*>(&Qt[d * ST_STRIDE + rg4]);
      s0[0] += kk0 * qv.x; s0[1] += kk0 * qv.y; s0[2] += kk0 * qv.z; s0[3] += kk0 * qv.w;
      s1[0] += kk1 * qv.x; s1[1] += kk1 * qv.y; s1[2] += kk1 * qv.z; s1[3] += kk1 * qv.w;
    }
    *reinterpret_cast<float4*>(&St[(kt + cgrp * 2 + 0) * ST_STRIDE + rg4]) =
        make_float4(s0[0], s0[1], s0[2], s0[3]);
    *reinterpret_cast<float4*>(&St[(kt + cgrp * 2 + 1) * ST_STRIDE + rg4]) =
        make_float4(s1[0], s1[1], s1[2], s1[3]);
  }
  __syncthreads();

  // --- phase 2: exact softmax per query row (column of St) ---
  {
    int r  = (tid >> 5) * 4 + ((tid & 31) >> 3);  // warp*4 + lane/8
    int ml = tid & 7;
    float mx = -1e30f;
    for (int m = ml; m < N_; m += 8)
      mx = fmaxf(mx, St[m * ST_STRIDE + r]);
#pragma unroll
    for (int o = 1; o < 8; o <<= 1)
      mx = fmaxf(mx, __shfl_xor_sync(0xffffffffu, mx, o));
    float sum = 0.f;
    for (int m = ml; m < N_; m += 8) {
      float e = __expf(St[m * ST_STRIDE + r] - mx);
      St[m * ST_STRIDE + r] = e;
      sum += e;
    }
#pragma unroll
    for (int o = 1; o < 8; o <<= 1)
      sum += __shfl_xor_sync(0xffffffffu, sum, o);
    if (ml == 0) RS[r] = 1.0f / sum;
  }

  // --- phase 3: O = P . V, normalize, write [B,N,D] layout ---
  const int r2  = (tid >> 4) << 1;    // 2 query rows
  const int hd4 = (tid & 15) << 2;    // 4 head dims
  float o0[4] = {0, 0, 0, 0}, o1[4] = {0, 0, 0, 0};
  for (int vt = 0; vt < N_; vt += 64) {
    __syncthreads();   // orders softmax writes + prior tile use before reload
#pragma unroll
    for (int cc = ld_c; cc < 64; cc += 16)
      *reinterpret_cast<float4*>(&KV[cc * KV_STRIDE + ld_d4]) =
          *reinterpret_cast<const float4*>(Vg + (size_t)(vt + cc) * HD_ + ld_d4);
    __syncthreads();
#pragma unroll 8
    for (int m = 0; m < 64; m++) {
      float p0 = St[(vt + m) * ST_STRIDE + r2 + 0];
      float p1 = St[(vt + m) * ST_STRIDE + r2 + 1];
      float4 vv = *reinterpret_cast<float4*>(&KV[m * KV_STRIDE + hd4]);
      o0[0] += p0 * vv.x; o0[1] += p0 * vv.y; o0[2] += p0 * vv.z; o0[3] += p0 * vv.w;
      o1[0] += p1 * vv.x; o1[1] += p1 * vv.y; o1[2] += p1 * vv.z; o1[3] += p1 * vv.w;
    }
  }
  float inv0 = RS[r2], inv1 = RS[r2 + 1];
  int b = bh / H_, h = bh - b * H_;
  size_t base = ((size_t)b * N_ + q0) * D_ + h * HD_;
  *reinterpret_cast<float4*>(&g_attn[base + (size_t)(r2 + 0) * D_ + hd4]) =
      make_float4(o0[0] * inv0, o0[1] * inv0, o0[2] * inv0, o0[3] * inv0);
  *reinterpret_cast<float4*>(&g_attn[base + (size_t)(r2 + 1) * D_ + hd4]) =
      make_float4(o1[0] * inv1, o1[1] * inv1, o1[2] * inv1, o1[3] * inv1);
}

// ---------------------------------------------------------------------------
extern "C" void kernel_launch(void* const* d_in, const int* in_sizes, int n_in,
                              void* d_out, int out_size)
{
  const float* x      = (const float*)d_in[0];   // [8,1024,768]
  const float* weight = (const float*)d_in[1];   // [8,1024]
  const float* W_qkv  = (const float*)d_in[2];   // [768,2304]
  const float* W_msa  = (const float*)d_in[3];   // [768,768]
  const float* b_msa  = (const float*)d_in[4];   // [768]
  float* out = (float*)d_out;                    // [8,1024,768]

  cudaFuncSetAttribute(attn_kernel,
                       cudaFuncAttributeMaxDynamicSharedMemorySize,
                       SM_FLOATS * sizeof(float));

  // 1) fused QKV projection + gate + head-major scatter
  gemm128<D3_, 0><<<dim3(D3_ / 128, ROWS / 128), 256>>>(x, W_qkv, weight, nullptr);
  // 2) softmax attention per head
  attn_kernel<<<dim3(N_ / 32, B_ * H_), 256, SM_FLOATS * sizeof(float)>>>();
  // 3) output projection + bias
  gemm128<D_, 1><<<dim3(D_ / 128, ROWS / 128), 256>>>(nullptr, W_msa, b_msa, out);
}

// round 3
// speedup vs baseline: 1.5531x; 1.5531x over previous
#include <cuda_runtime.h>
#include <cuda_bf16.h>

#define B_   8
#define N_   1024
#define D_   768
#define H_   12
#define HD_  64
#define ROWS (B_ * N_)      // 8192
#define D3_  (3 * D_)       // 2304
#define SCALE_ 0.125f
#define NBH  (B_ * H_)      // 96

// ---------------- bf16 split scratch (alloc-free rule: device globals) -----
__device__ __align__(16) unsigned short g_Qh[NBH * N_ * HD_];
__device__ __align__(16) unsigned short g_Ql[NBH * N_ * HD_];
__device__ __align__(16) unsigned short g_Kh[NBH * N_ * HD_];
__device__ __align__(16) unsigned short g_Kl[NBH * N_ * HD_];
__device__ __align__(16) unsigned short g_Vth[NBH * HD_ * N_];  // [bh][hd][key]
__device__ __align__(16) unsigned short g_Vtl[NBH * HD_ * N_];
__device__ __align__(16) unsigned short g_Ah[ROWS * D_];        // attn out hi
__device__ __align__(16) unsigned short g_Al[ROWS * D_];        // attn out lo

// ---------------- helpers --------------------------------------------------
__device__ __forceinline__ unsigned short bf16_rn(float x) {
  unsigned u = __float_as_uint(x);
  return (unsigned short)((u + 0x7fffu + ((u >> 16) & 1u)) >> 16);
}
__device__ __forceinline__ float bf16_tof(unsigned short h) {
  return __uint_as_float(((unsigned)h) << 16);
}
__device__ __forceinline__ void splitf(float x, unsigned short& h, unsigned short& l) {
  h = bf16_rn(x);
  l = bf16_rn(x - bf16_tof(h));
}

// D = A(16x16 bf16 row) * B(16x8 bf16 col) + D, fp32 accum
__device__ __forceinline__ void mma16816(float* c, const unsigned* a, const unsigned* b) {
  asm volatile(
      "mma.sync.aligned.m16n8k16.row.col.f32.bf16.bf16.f32 "
      "{%0,%1,%2,%3}, {%4,%5,%6,%7}, {%8,%9}, {%0,%1,%2,%3};\n"
      : "+f"(c[0]), "+f"(c[1]), "+f"(c[2]), "+f"(c[3])
      : "r"(a[0]), "r"(a[1]), "r"(a[2]), "r"(a[3]), "r"(b[0]), "r"(b[1]));
}

// ---------------------------------------------------------------------------
// Split-bf16 tensor-core GEMM: C[8192 x NCOLS] = A[8192x768] * B[768 x LDB]
// CTA 128x128, K-step 32, 256 threads (8 warps as 2m x 4n, warp tile 64x32).
// MODE 0: A = x fp32 (split at load); epilogue gate + scale + QKV split-scatter.
// MODE 1: A = g_Ah/g_Al bf16; epilogue + bias -> fp32 out.
// ---------------------------------------------------------------------------
template <int LDB, int MODE>
__global__ __launch_bounds__(256) void gemm_mma(
    const float* __restrict__ A, const float* __restrict__ Bm,
    const float* __restrict__ aux, float* __restrict__ C)
{
  __shared__ unsigned short As_h[128 * 40], As_l[128 * 40];
  __shared__ unsigned short Bs_h[128 * 40], Bs_l[128 * 40];

  const int tid = threadIdx.x;
  const int lane = tid & 31, warp = tid >> 5;
  const int g = lane >> 2, tg = lane & 3;
  const int wm = (warp >> 2) * 64, wn = (warp & 3) * 32;
  const int bx = blockIdx.x, by = blockIdx.y;

  const int aRow = tid >> 1, aK = (tid & 1) * 16;   // A tile: 128 x 32
  const int bK = tid >> 3,  bN = (tid & 7) * 4;     // B tile: 32 x 128

  float acc[4][4][4];
#pragma unroll
  for (int i = 0; i < 4; i++)
#pragma unroll
    for (int j = 0; j < 4; j++)
#pragma unroll
      for (int c = 0; c < 4; c++) acc[i][j][c] = 0.f;

  float4 pa[4], pb[4];
  uint4 pah[2], pal[2];

  auto load_tile = [&](int k0) {
    if constexpr (MODE == 0) {
#pragma unroll
      for (int j = 0; j < 4; j++)
        pa[j] = *reinterpret_cast<const float4*>(
            &A[(size_t)(by * 128 + aRow) * D_ + k0 + aK + j * 4]);
    } else {
      const size_t ab = (size_t)(by * 128 + aRow) * D_ + k0 + aK;
      pah[0] = *reinterpret_cast<const uint4*>(&g_Ah[ab]);
      pah[1] = *reinterpret_cast<const uint4*>(&g_Ah[ab + 8]);
      pal[0] = *reinterpret_cast<const uint4*>(&g_Al[ab]);
      pal[1] = *reinterpret_cast<const uint4*>(&g_Al[ab + 8]);
    }
#pragma unroll
    for (int j = 0; j < 4; j++)
      pb[j] = *reinterpret_cast<const float4*>(
          &Bm[(size_t)(k0 + bK) * LDB + bx * 128 + bN + j * 32]);
  };

  auto store_tile = [&]() {
    if constexpr (MODE == 0) {
#pragma unroll
      for (int j = 0; j < 4; j++) {
        const int k = aK + j * 4;
        float f[4] = {pa[j].x, pa[j].y, pa[j].z, pa[j].w};
#pragma unroll
        for (int t = 0; t < 4; t++) {
          unsigned short h, l;
          splitf(f[t], h, l);
          As_h[aRow * 40 + k + t] = h;
          As_l[aRow * 40 + k + t] = l;
        }
      }
    } else {
      *reinterpret_cast<uint4*>(&As_h[aRow * 40 + aK])     = pah[0];
      *reinterpret_cast<uint4*>(&As_h[aRow * 40 + aK + 8]) = pah[1];
      *reinterpret_cast<uint4*>(&As_l[aRow * 40 + aK])     = pal[0];
      *reinterpret_cast<uint4*>(&As_l[aRow * 40 + aK + 8]) = pal[1];
    }
#pragma unroll
    for (int j = 0; j < 4; j++) {
      const int nb = bN + j * 32;
      float f[4] = {pb[j].x, pb[j].y, pb[j].z, pb[j].w};
#pragma unroll
      for (int t = 0; t < 4; t++) {
        unsigned short h, l;
        splitf(f[t], h, l);
        Bs_h[(nb + t) * 40 + bK] = h;   // transposed: [n][k]
        Bs_l[(nb + t) * 40 + bK] = l;
      }
    }
  };

  load_tile(0);
  for (int k0 = 0; k0 < D_; k0 += 32) {
    __syncthreads();
    store_tile();
    __syncthreads();
    if (k0 + 32 < D_) load_tile(k0 + 32);

#pragma unroll
    for (int kk = 0; kk < 32; kk += 16) {
      unsigned Ahf[4][4], Alf[4][4], Bhf[4][2], Blf[4][2];
#pragma unroll
      for (int i = 0; i < 4; i++) {
        const int m = wm + i * 16 + g;
        Ahf[i][0] = *reinterpret_cast<const unsigned*>(&As_h[m * 40 + kk + 2 * tg]);
        Ahf[i][1] = *reinterpret_cast<const unsigned*>(&As_h[(m + 8) * 40 + kk + 2 * tg]);
        Ahf[i][2] = *reinterpret_cast<const unsigned*>(&As_h[m * 40 + kk + 8 + 2 * tg]);
        Ahf[i][3] = *reinterpret_cast<const unsigned*>(&As_h[(m + 8) * 40 + kk + 8 + 2 * tg]);
        Alf[i][0] = *reinterpret_cast<const unsigned*>(&As_l[m * 40 + kk + 2 * tg]);
        Alf[i][1] = *reinterpret_cast<const unsigned*>(&As_l[(m + 8) * 40 + kk + 2 * tg]);
        Alf[i][2] = *reinterpret_cast<const unsigned*>(&As_l[m * 40 + kk + 8 + 2 * tg]);
        Alf[i][3] = *reinterpret_cast<const unsigned*>(&As_l[(m + 8) * 40 + kk + 8 + 2 * tg]);
      }
#pragma unroll
      for (int j = 0; j < 4; j++) {
        const int n = wn + j * 8 + g;
        Bhf[j][0] = *reinterpret_cast<const unsigned*>(&Bs_h[n * 40 + kk + 2 * tg]);
        Bhf[j][1] = *reinterpret_cast<const unsigned*>(&Bs_h[n * 40 + kk + 8 + 2 * tg]);
        Blf[j][0] = *reinterpret_cast<const unsigned*>(&Bs_l[n * 40 + kk + 2 * tg]);
        Blf[j][1] = *reinterpret_cast<const unsigned*>(&Bs_l[n * 40 + kk + 8 + 2 * tg]);
      }
#pragma unroll
      for (int i = 0; i < 4; i++)
#pragma unroll
        for (int j = 0; j < 4; j++) {
          mma16816(acc[i][j], Ahf[i], Bhf[j]);
          mma16816(acc[i][j], Ahf[i], Blf[j]);
          mma16816(acc[i][j], Alf[i], Bhf[j]);
        }
    }
  }

  // ---------------- epilogue ----------------
  if constexpr (MODE == 0) {
    const int which = bx / 6;   // 0=Q 1=K 2=V  (768 = 6 tiles of 128)
#pragma unroll
    for (int i = 0; i < 4; i++) {
#pragma unroll
      for (int half = 0; half < 2; half++) {
        const int m = by * 128 + wm + i * 16 + g + half * 8;
        const float gate = aux[m];
        const int b = m >> 10, tok = m & 1023;
#pragma unroll
        for (int j = 0; j < 4; j++) {
          const int col = bx * 128 + wn + j * 8 + 2 * tg;
          const int dd = col - which * D_;
          const int h = dd >> 6, hd = dd & 63;
          const int bh = b * H_ + h;
          float v0 = acc[i][j][half * 2 + 0] * gate;
          float v1 = acc[i][j][half * 2 + 1] * gate;
          if (which == 0) { v0 *= SCALE_; v1 *= SCALE_; }
          unsigned short h0, l0, h1, l1;
          splitf(v0, h0, l0); splitf(v1, h1, l1);
          if (which == 0) {
            const size_t idx = ((size_t)bh * N_ + tok) * HD_ + hd;
            *reinterpret_cast<unsigned*>(&g_Qh[idx]) = (unsigned)h0 | ((unsigned)h1 << 16);
            *reinterpret_cast<unsigned*>(&g_Ql[idx]) = (unsigned)l0 | ((unsigned)l1 << 16);
          } else if (which == 1) {
            const size_t idx = ((size_t)bh * N_ + tok) * HD_ + hd;
            *reinterpret_cast<unsigned*>(&g_Kh[idx]) = (unsigned)h0 | ((unsigned)h1 << 16);
            *reinterpret_cast<unsigned*>(&g_Kl[idx]) = (unsigned)l0 | ((unsigned)l1 << 16);
          } else {
            const size_t r0 = ((size_t)bh * HD_ + hd) * N_ + tok;   // transposed
            g_Vth[r0] = h0; g_Vth[r0 + N_] = h1;
            g_Vtl[r0] = l0; g_Vtl[r0 + N_] = l1;
          }
        }
      }
    }
  } else {
#pragma unroll
    for (int i = 0; i < 4; i++)
#pragma unroll
      for (int half = 0; half < 2; half++) {
        const int m = by * 128 + wm + i * 16 + g + half * 8;
#pragma unroll
        for (int j = 0; j < 4; j++) {
          const int col = bx * 128 + wn + j * 8 + 2 * tg;
          float2 o;
          o.x = acc[i][j][half * 2 + 0] + aux[col];
          o.y = acc[i][j][half * 2 + 1] + aux[col + 1];
          *reinterpret_cast<float2*>(&C[(size_t)m * D_ + col]) = o;
        }
      }
  }
}

// ---------------------------------------------------------------------------
// Attention: block = 32 queries of one (b,h). S[32][1024] fp32 in SMEM via
// split-bf16 mma; exact full-row softmax; P split+packed in place; PV mma.
// ---------------------------------------------------------------------------
#define SROW 1032
#define ATT_SMEM (32 * SROW * 4)

__global__ __launch_bounds__(256) void attn_mma()
{
  extern __shared__ __align__(16) float sm[];   // S [32][1032]
  const int tid = threadIdx.x, lane = tid & 31, warp = tid >> 5;
  const int g = lane >> 2, tg = lane & 3;
  const int bh = blockIdx.y;
  const int q0 = blockIdx.x * 32;
  const size_t qbase = ((size_t)bh * N_ + q0) * HD_;
  const size_t kbase = (size_t)bh * N_ * HD_;
  const size_t vbase = (size_t)bh * HD_ * N_;

  // --- Q fragments (held for whole kernel): 2 m16 x 4 k16, hi+lo ---
  unsigned qh[2][4][4], ql[2][4][4];
#pragma unroll
  for (int i = 0; i < 2; i++)
#pragma unroll
    for (int c = 0; c < 4; c++) {
      const size_t r0 = qbase + (size_t)(i * 16 + g) * HD_ + c * 16 + 2 * tg;
      const size_t r8 = r0 + 8 * HD_;
      qh[i][c][0] = *reinterpret_cast<const unsigned*>(&g_Qh[r0]);
      qh[i][c][1] = *reinterpret_cast<const unsigned*>(&g_Qh[r8]);
      qh[i][c][2] = *reinterpret_cast<const unsigned*>(&g_Qh[r0 + 8]);
      qh[i][c][3] = *reinterpret_cast<const unsigned*>(&g_Qh[r8 + 8]);
      ql[i][c][0] = *reinterpret_cast<const unsigned*>(&g_Ql[r0]);
      ql[i][c][1] = *reinterpret_cast<const unsigned*>(&g_Ql[r8]);
      ql[i][c][2] = *reinterpret_cast<const unsigned*>(&g_Ql[r0 + 8]);
      ql[i][c][3] = *reinterpret_cast<const unsigned*>(&g_Ql[r0 + 8 + 8 * HD_]);
    }

  // --- phase 1: S = Q K^T (warp w covers keys [w*128, w*128+128) ) ---
#pragma unroll 1
  for (int j = 0; j < 16; j++) {
    const int key = warp * 128 + j * 8;
    unsigned kbh[4][2], kbl[4][2];
#pragma unroll
    for (int c = 0; c < 4; c++) {
      const size_t kb = kbase + (size_t)(key + g) * HD_ + c * 16 + 2 * tg;
      kbh[c][0] = *reinterpret_cast<const unsigned*>(&g_Kh[kb]);
      kbh[c][1] = *reinterpret_cast<const unsigned*>(&g_Kh[kb + 8]);
      kbl[c][0] = *reinterpret_cast<const unsigned*>(&g_Kl[kb]);
      kbl[c][1] = *reinterpret_cast<const unsigned*>(&g_Kl[kb + 8]);
    }
    float a0[4] = {0, 0, 0, 0}, a1[4] = {0, 0, 0, 0};
#pragma unroll
    for (int c = 0; c < 4; c++) {
      mma16816(a0, qh[0][c], kbh[c]);
      mma16816(a0, qh[0][c], kbl[c]);
      mma16816(a0, ql[0][c], kbh[c]);
      mma16816(a1, qh[1][c], kbh[c]);
      mma16816(a1, qh[1][c], kbl[c]);
      mma16816(a1, ql[1][c], kbh[c]);
    }
    const int colk = key + 2 * tg;
    *reinterpret_cast<float2*>(&sm[(g)      * SROW + colk]) = make_float2(a0[0], a0[1]);
    *reinterpret_cast<float2*>(&sm[(g + 8)  * SROW + colk]) = make_float2(a0[2], a0[3]);
    *reinterpret_cast<float2*>(&sm[(16 + g) * SROW + colk]) = make_float2(a1[0], a1[1]);
    *reinterpret_cast<float2*>(&sm[(24 + g) * SROW + colk]) = make_float2(a1[2], a1[3]);
  }
  __syncthreads();

  // --- phase 2: exact softmax; write P packed (hi | lo<<16) in place ---
  {
    const int r = tid >> 3, ml = tid & 7;
    float* row = sm + r * SROW;
    float mx = -1e30f;
    for (int k = ml * 4; k < N_; k += 32) {
      float4 v = *reinterpret_cast<float4*>(&row[k]);
      mx = fmaxf(mx, fmaxf(fmaxf(v.x, v.y), fmaxf(v.z, v.w)));
    }
#pragma unroll
    for (int o = 1; o < 8; o <<= 1) mx = fmaxf(mx, __shfl_xor_sync(0xffffffffu, mx, o));
    float s = 0.f;
    for (int k = ml * 4; k < N_; k += 32) {
      float4 v = *reinterpret_cast<float4*>(&row[k]);
      v.x = __expf(v.x - mx); v.y = __expf(v.y - mx);
      v.z = __expf(v.z - mx); v.w = __expf(v.w - mx);
      s += v.x + v.y + v.z + v.w;
      *reinterpret_cast<float4*>(&row[k]) = v;
    }
#pragma unroll
    for (int o = 1; o < 8; o <<= 1) s += __shfl_xor_sync(0xffffffffu, s, o);
    const float inv = 1.f / s;
    unsigned* urow = reinterpret_cast<unsigned*>(row);
    for (int k = ml * 4; k < N_; k += 32) {
      float4 v = *reinterpret_cast<float4*>(&row[k]);
      float p[4] = {v.x * inv, v.y * inv, v.z * inv, v.w * inv};
      unsigned u[4];
#pragma unroll
      for (int t = 0; t < 4; t++) {
        unsigned short h, l;
        splitf(p[t], h, l);
        u[t] = (unsigned)h | ((unsigned)l << 16);
      }
      urow[k] = u[0]; urow[k + 1] = u[1]; urow[k + 2] = u[2]; urow[k + 3] = u[3];
    }
  }
  __syncthreads();

  // --- phase 3: O = P V  (warp w covers hd [w*8, w*8+8) ) ---
  const unsigned* Sp = reinterpret_cast<const unsigned*>(sm);
  float oacc[2][4];
#pragma unroll
  for (int i = 0; i < 2; i++)
#pragma unroll
    for (int c = 0; c < 4; c++) oacc[i][c] = 0.f;
  const int n0 = warp * 8;

#pragma unroll 1
  for (int t = 0; t < 64; t++) {
    const int kb0 = t * 16;
    unsigned vbh[2], vbl[2];
    const size_t vb = vbase + (size_t)(n0 + g) * N_ + kb0 + 2 * tg;
    vbh[0] = *reinterpret_cast<const unsigned*>(&g_Vth[vb]);
    vbh[1] = *reinterpret_cast<const unsigned*>(&g_Vth[vb + 8]);
    vbl[0] = *reinterpret_cast<const unsigned*>(&g_Vtl[vb]);
    vbl[1] = *reinterpret_cast<const unsigned*>(&g_Vtl[vb + 8]);
#pragma unroll
    for (int i = 0; i < 2; i++) {
      const unsigned* p0 = &Sp[(size_t)(i * 16 + g) * SROW + kb0 + 2 * tg];
      const unsigned* p8 = &Sp[(size_t)(i * 16 + g + 8) * SROW + kb0 + 2 * tg];
      const uint2 s00 = *reinterpret_cast<const uint2*>(p0);
      const uint2 s08 = *reinterpret_cast<const uint2*>(p0 + 8);
      const uint2 s80 = *reinterpret_cast<const uint2*>(p8);
      const uint2 s88 = *reinterpret_cast<const uint2*>(p8 + 8);
      unsigned Ahf[4] = {__byte_perm(s00.x, s00.y, 0x5410),
                         __byte_perm(s80.x, s80.y, 0x5410),
                         __byte_perm(s08.x, s08.y, 0x5410),
                         __byte_perm(s88.x, s88.y, 0x5410)};
      unsigned Alf[4] = {__byte_perm(s00.x, s00.y, 0x7632),
                         __byte_perm(s80.x, s80.y, 0x7632),
                         __byte_perm(s08.x, s08.y, 0x7632),
                         __byte_perm(s88.x, s88.y, 0x7632)};
      mma16816(oacc[i], Ahf, vbh);
      mma16816(oacc[i], Ahf, vbl);
      mma16816(oacc[i], Alf, vbh);
    }
  }

  // --- write O as split bf16 (for GEMM2) ---
  const int b = bh / H_, h = bh - (bh / H_) * H_;
#pragma unroll
  for (int i = 0; i < 2; i++) {
    const int row0 = b * N_ + q0 + i * 16 + g;
    const size_t o0 = (size_t)row0 * D_ + h * HD_ + n0 + 2 * tg;
    unsigned short h0, l0, h1, l1;
    splitf(oacc[i][0], h0, l0); splitf(oacc[i][1], h1, l1);
    *reinterpret_cast<unsigned*>(&g_Ah[o0]) = (unsigned)h0 | ((unsigned)h1 << 16);
    *reinterpret_cast<unsigned*>(&g_Al[o0]) = (unsigned)l0 | ((unsigned)l1 << 16);
    splitf(oacc[i][2], h0, l0); splitf(oacc[i][3], h1, l1);
    *reinterpret_cast<unsigned*>(&g_Ah[o0 + (size_t)8 * D_]) = (unsigned)h0 | ((unsigned)h1 << 16);
    *reinterpret_cast<unsigned*>(&g_Al[o0 + (size_t)8 * D_]) = (unsigned)l0 | ((unsigned)l1 << 16);
  }
}

// ---------------------------------------------------------------------------
extern "C" void kernel_launch(void* const* d_in, const int* in_sizes, int n_in,
                              void* d_out, int out_size)
{
  const float* x      = (const float*)d_in[0];
  const float* weight = (const float*)d_in[1];
  const float* W_qkv  = (const float*)d_in[2];
  const float* W_msa  = (const float*)d_in[3];
  const float* b_msa  = (const float*)d_in[4];
  float* out = (float*)d_out;

  cudaFuncSetAttribute(attn_mma, cudaFuncAttributeMaxDynamicSharedMemorySize,
                       ATT_SMEM);

  gemm_mma<D3_, 0><<<dim3(D3_ / 128, ROWS / 128), 256>>>(x, W_qkv, weight, nullptr);
  attn_mma<<<dim3(N_ / 32, NBH), 256, ATT_SMEM>>>();
  gemm_mma<D_, 1><<<dim3(D_ / 128, ROWS / 128), 256>>>(nullptr, W_msa, b_msa, out);
}

// round 6
// speedup vs baseline: 2.7618x; 1.7783x over previous
#include <cuda_runtime.h>
#include <cuda_bf16.h>

#define B_   8
#define N_   1024
#define D_   768
#define H_   12
#define HD_  64
#define ROWS (B_ * N_)      // 8192
#define D3_  (3 * D_)       // 2304
#define SCALE_ 0.125f
#define NBH  (B_ * H_)      // 96

// ---------------- split bf16 scratch (alloc-free rule: device globals) -----
__device__ __align__(16) unsigned short g_Xh[ROWS * D_];
__device__ __align__(16) unsigned short g_Xl[ROWS * D_];
__device__ __align__(16) unsigned short g_Wqh[D_ * D3_];
__device__ __align__(16) unsigned short g_Wql[D_ * D3_];
__device__ __align__(16) unsigned short g_Wmh[D_ * D_];
__device__ __align__(16) unsigned short g_Wml[D_ * D_];
__device__ __align__(16) unsigned short g_Qh[NBH * N_ * HD_];
__device__ __align__(16) unsigned short g_Ql[NBH * N_ * HD_];
__device__ __align__(16) unsigned short g_Kh[NBH * N_ * HD_];
__device__ __align__(16) unsigned short g_Kl[NBH * N_ * HD_];
__device__ __align__(16) unsigned short g_Vth[NBH * HD_ * N_];  // [bh][hd][key]
__device__ __align__(16) unsigned short g_Vtl[NBH * HD_ * N_];
__device__ __align__(16) unsigned short g_Ah[ROWS * D_];        // attn out hi
__device__ __align__(16) unsigned short g_Al[ROWS * D_];        // attn out lo

// ---------------- helpers --------------------------------------------------
__device__ __forceinline__ unsigned short bf16_rn(float x) {
  unsigned u = __float_as_uint(x);
  return (unsigned short)((u + 0x7fffu + ((u >> 16) & 1u)) >> 16);
}
__device__ __forceinline__ float bf16_tof(unsigned short h) {
  return __uint_as_float(((unsigned)h) << 16);
}
__device__ __forceinline__ void splitf(float x, unsigned short& h, unsigned short& l) {
  h = bf16_rn(x);
  l = bf16_rn(x - bf16_tof(h));
}
__device__ __forceinline__ void mma16816(float* c, const unsigned* a,
                                         unsigned b0, unsigned b1) {
  asm volatile(
      "mma.sync.aligned.m16n8k16.row.col.f32.bf16.bf16.f32 "
      "{%0,%1,%2,%3}, {%4,%5,%6,%7}, {%8,%9}, {%0,%1,%2,%3};\n"
      : "+f"(c[0]), "+f"(c[1]), "+f"(c[2]), "+f"(c[3])
      : "r"(a[0]), "r"(a[1]), "r"(a[2]), "r"(a[3]), "r"(b0), "r"(b1));
}
__device__ __forceinline__ void ldsm4(unsigned* r, unsigned a) {
  asm volatile("ldmatrix.sync.aligned.m8n8.x4.shared.b16 {%0,%1,%2,%3}, [%4];\n"
               : "=r"(r[0]), "=r"(r[1]), "=r"(r[2]), "=r"(r[3]) : "r"(a));
}
__device__ __forceinline__ void ldsm4t(unsigned* r, unsigned a) {
  asm volatile("ldmatrix.sync.aligned.m8n8.x4.trans.shared.b16 {%0,%1,%2,%3}, [%4];\n"
               : "=r"(r[0]), "=r"(r[1]), "=r"(r[2]), "=r"(r[3]) : "r"(a));
}
__device__ __forceinline__ void cp16(void* smem, const void* gmem) {
  unsigned s = (unsigned)__cvta_generic_to_shared(smem);
  asm volatile("cp.async.cg.shared.global [%0], [%1], 16;\n" :: "r"(s), "l"(gmem));
}

// ---------------- pre-split: fp32 -> hi/lo bf16 ----------------------------
__global__ void split4(const float4* __restrict__ src, uint2* __restrict__ dh,
                       uint2* __restrict__ dl, int n4) {
  int i = blockIdx.x * blockDim.x + threadIdx.x;
  if (i >= n4) return;
  float4 v = src[i];
  unsigned short h0, l0, h1, l1, h2, l2, h3, l3;
  splitf(v.x, h0, l0); splitf(v.y, h1, l1);
  splitf(v.z, h2, l2); splitf(v.w, h3, l3);
  dh[i] = make_uint2((unsigned)h0 | ((unsigned)h1 << 16),
                     (unsigned)h2 | ((unsigned)h3 << 16));
  dl[i] = make_uint2((unsigned)l0 | ((unsigned)l1 << 16),
                     (unsigned)l2 | ((unsigned)l3 << 16));
}

// ---------------------------------------------------------------------------
// Split-bf16 GEMM with cp.async double-buffer + ldmatrix.
// CTA 128x128, kstep 32, 8 warps (2m x 4n), warp tile 64x32.
// SMEM (u16): Ah[2][128][40] | Al | Bh[2][32][136] | Bl  = 75,776 B
// ---------------------------------------------------------------------------
#define GEMM_SMEM 75776

template <int LDB, int MODE>
__global__ __launch_bounds__(256) void gemm_mma(
    const unsigned short* __restrict__ Agh, const unsigned short* __restrict__ Agl,
    const unsigned short* __restrict__ Bgh, const unsigned short* __restrict__ Bgl,
    const float* __restrict__ aux, float* __restrict__ C)
{
  extern __shared__ __align__(16) unsigned short smem_u16[];
  const int tid = threadIdx.x, lane = tid & 31, warp = tid >> 5;
  const int g = lane >> 2, tg = lane & 3;
  const int wm = (warp >> 2) * 64, wn = (warp & 3) * 32;
  const int bx = blockIdx.x, by = blockIdx.y;

  float acc[4][4][4] = {};

  const unsigned sbase = (unsigned)__cvta_generic_to_shared(smem_u16);
  const unsigned aoff = ((wm + (lane & 15)) * 40 + (lane >> 4) * 8) * 2;
  const unsigned boff = ((lane & 15) * 136 + wn + (lane >> 4) * 8) * 2;

  auto load_stage = [&](int k0, int st) {
    unsigned short* dAh = smem_u16 + st * 5120;
    unsigned short* dAl = smem_u16 + 10240 + st * 5120;
    unsigned short* dBh = smem_u16 + 20480 + st * 4352;
    unsigned short* dBl = smem_u16 + 29184 + st * 4352;
#pragma unroll
    for (int t = 0; t < 2; t++) {
      int c = tid + t * 256;
      int ar = c >> 2, ak = (c & 3) * 8;
      size_t ga = (size_t)(by * 128 + ar) * D_ + k0 + ak;
      cp16(dAh + ar * 40 + ak, Agh + ga);
      cp16(dAl + ar * 40 + ak, Agl + ga);
      int br = c >> 4, bn = (c & 15) * 8;
      size_t gb = (size_t)(k0 + br) * LDB + bx * 128 + bn;
      cp16(dBh + br * 136 + bn, Bgh + gb);
      cp16(dBl + br * 136 + bn, Bgl + gb);
    }
    asm volatile("cp.async.commit_group;\n" ::: "memory");
  };

  load_stage(0, 0);
  for (int it = 0; it < 24; it++) {
    if (it + 1 < 24) {
      load_stage((it + 1) * 32, (it + 1) & 1);
      asm volatile("cp.async.wait_group 1;\n" ::: "memory");
    } else {
      asm volatile("cp.async.wait_group 0;\n" ::: "memory");
    }
    __syncthreads();
    const int st = it & 1;
    const unsigned sAh = sbase + st * 10240;
    const unsigned sAl = sbase + 20480 + st * 10240;
    const unsigned sBh = sbase + 40960 + st * 8704;
    const unsigned sBl = sbase + 58368 + st * 8704;
#pragma unroll
    for (int kk = 0; kk < 2; kk++) {
      unsigned ah[4][4], al[4][4], bh[2][4], bl[2][4];
#pragma unroll
      for (int i = 0; i < 4; i++) {
        ldsm4(ah[i], sAh + aoff + i * 1280 + kk * 32);
        ldsm4(al[i], sAl + aoff + i * 1280 + kk * 32);
      }
#pragma unroll
      for (int jj = 0; jj < 2; jj++) {
        ldsm4t(bh[jj], sBh + boff + kk * 4352 + jj * 32);
        ldsm4t(bl[jj], sBl + boff + kk * 4352 + jj * 32);
      }
#pragma unroll
      for (int i = 0; i < 4; i++)
#pragma unroll
        for (int jj = 0; jj < 2; jj++) {
          mma16816(acc[i][2 * jj], ah[i], bh[jj][0], bh[jj][1]);
          mma16816(acc[i][2 * jj], ah[i], bl[jj][0], bl[jj][1]);
          mma16816(acc[i][2 * jj], al[i], bh[jj][0], bh[jj][1]);
          mma16816(acc[i][2 * jj + 1], ah[i], bh[jj][2], bh[jj][3]);
          mma16816(acc[i][2 * jj + 1], ah[i], bl[jj][2], bl[jj][3]);
          mma16816(acc[i][2 * jj + 1], al[i], bh[jj][2], bh[jj][3]);
        }
    }
    __syncthreads();
  }

  // ---------------- epilogue ----------------
  if constexpr (MODE == 0) {
    const int which = bx / 6;   // 0=Q 1=K 2=V
#pragma unroll
    for (int i = 0; i < 4; i++) {
#pragma unroll
      for (int half = 0; half < 2; half++) {
        const int m = by * 128 + wm + i * 16 + g + half * 8;
        const float gate = aux[m];
        const int b = m >> 10, tok = m & 1023;
#pragma unroll
        for (int j = 0; j < 4; j++) {
          const int col = bx * 128 + wn + j * 8 + 2 * tg;
          const int dd = col - which * D_;
          const int h = dd >> 6, hd = dd & 63;
          const int bh = b * H_ + h;
          float v0 = acc[i][j][half * 2 + 0] * gate;
          float v1 = acc[i][j][half * 2 + 1] * gate;
          if (which == 0) { v0 *= SCALE_; v1 *= SCALE_; }
          unsigned short h0, l0, h1, l1;
          splitf(v0, h0, l0); splitf(v1, h1, l1);
          if (which == 0) {
            const size_t idx = ((size_t)bh * N_ + tok) * HD_ + hd;
            *reinterpret_cast<unsigned*>(&g_Qh[idx]) = (unsigned)h0 | ((unsigned)h1 << 16);
            *reinterpret_cast<unsigned*>(&g_Ql[idx]) = (unsigned)l0 | ((unsigned)l1 << 16);
          } else if (which == 1) {
            const size_t idx = ((size_t)bh * N_ + tok) * HD_ + hd;
            *reinterpret_cast<unsigned*>(&g_Kh[idx]) = (unsigned)h0 | ((unsigned)h1 << 16);
            *reinterpret_cast<unsigned*>(&g_Kl[idx]) = (unsigned)l0 | ((unsigned)l1 << 16);
          } else {
            const size_t r0 = ((size_t)bh * HD_ + hd) * N_ + tok;
            g_Vth[r0] = h0; g_Vth[r0 + N_] = h1;
            g_Vtl[r0] = l0; g_Vtl[r0 + N_] = l1;
          }
        }
      }
    }
  } else {
#pragma unroll
    for (int i = 0; i < 4; i++)
#pragma unroll
      for (int half = 0; half < 2; half++) {
        const int m = by * 128 + wm + i * 16 + g + half * 8;
#pragma unroll
        for (int j = 0; j < 4; j++) {
          const int col = bx * 128 + wn + j * 8 + 2 * tg;
          float2 o;
          o.x = acc[i][j][half * 2 + 0] + aux[col];
          o.y = acc[i][j][half * 2 + 1] + aux[col + 1];
          *reinterpret_cast<float2*>(&C[(size_t)m * D_ + col]) = o;
        }
      }
  }
}

// ---------------------------------------------------------------------------
// Attention: 32 queries/block. S[32][1032] fp32 in SMEM. K/V tiles (128 keys)
// staged via cp.async double-buffer + ldmatrix. Exact full-row softmax,
// P packed (hi|lo<<16) in place, PV via mma.
// Stage layout (u16): hi plane at +0, lo plane at +9216 (= +18432 BYTES).
// SMEM: S 132,096 B + 2 KV stages x 36,864 B = 205,824 B
// ---------------------------------------------------------------------------
#define SROW 1032
#define ATT_S_BYTES (32 * SROW * 4)
#define ATT_STG 36864
#define ATT_LO 18432          // BYTE offset of lo plane within a stage
#define ATT_SMEM (ATT_S_BYTES + 2 * ATT_STG)

__global__ __launch_bounds__(256) void attn_mma()
{
  extern __shared__ __align__(16) unsigned char smem_raw[];
  float* S = (float*)smem_raw;
  unsigned* Sp = (unsigned*)smem_raw;
  unsigned short* KV = (unsigned short*)(smem_raw + ATT_S_BYTES);
  const unsigned kvbase = (unsigned)__cvta_generic_to_shared(KV);

  const int tid = threadIdx.x, lane = tid & 31, warp = tid >> 5;
  const int g = lane >> 2, tg = lane & 3;
  const int bh = blockIdx.y;
  const int q0 = blockIdx.x * 32;
  const size_t qbase = ((size_t)bh * N_ + q0) * HD_;
  const size_t kbase = (size_t)bh * N_ * HD_;
  const size_t vbase = (size_t)bh * HD_ * N_;

  auto load_k = [&](int kt, int st) {
    unsigned short* dst = KV + st * 18432;
    const unsigned short* sh = g_Kh + kbase + (size_t)kt * 128 * HD_;
    const unsigned short* sl = g_Kl + kbase + (size_t)kt * 128 * HD_;
#pragma unroll
    for (int t = 0; t < 4; t++) {
      int c = tid + t * 256;
      int row = c >> 3, ko = (c & 7) * 8;
      cp16(dst + row * 72 + ko, sh + row * HD_ + ko);
      cp16(dst + 9216 + row * 72 + ko, sl + row * HD_ + ko);
    }
    asm volatile("cp.async.commit_group;\n" ::: "memory");
  };
  auto load_v = [&](int vt, int st) {
    unsigned short* dst = KV + st * 18432;
    const unsigned short* sh = g_Vth + vbase + vt * 128;
    const unsigned short* sl = g_Vtl + vbase + vt * 128;
#pragma unroll
    for (int t = 0; t < 4; t++) {
      int c = tid + t * 256;
      int row = c >> 4, no = (c & 15) * 8;
      cp16(dst + row * 136 + no, sh + (size_t)row * N_ + no);
      cp16(dst + 9216 + row * 136 + no, sl + (size_t)row * N_ + no);
    }
    asm volatile("cp.async.commit_group;\n" ::: "memory");
  };

  load_k(0, 0);

  // --- Q fragments (resident): 2 m16-tiles x 4 k16-chunks, hi+lo ---
  unsigned qh[2][4][4], ql[2][4][4];
#pragma unroll
  for (int i = 0; i < 2; i++)
#pragma unroll
    for (int c = 0; c < 4; c++) {
      const size_t r0 = qbase + (size_t)(i * 16 + g) * HD_ + c * 16 + 2 * tg;
      const size_t r8 = r0 + 8 * HD_;
      qh[i][c][0] = *reinterpret_cast<const unsigned*>(&g_Qh[r0]);
      qh[i][c][1] = *reinterpret_cast<const unsigned*>(&g_Qh[r8]);
      qh[i][c][2] = *reinterpret_cast<const unsigned*>(&g_Qh[r0 + 8]);
      qh[i][c][3] = *reinterpret_cast<const unsigned*>(&g_Qh[r8 + 8]);
      ql[i][c][0] = *reinterpret_cast<const unsigned*>(&g_Ql[r0]);
      ql[i][c][1] = *reinterpret_cast<const unsigned*>(&g_Ql[r8]);
      ql[i][c][2] = *reinterpret_cast<const unsigned*>(&g_Ql[r0 + 8]);
      ql[i][c][3] = *reinterpret_cast<const unsigned*>(&g_Ql[r8 + 8]);
    }

  // --- phase 1: S = Q K^T  (warp covers 16 keys per 128-key tile) ---
  const unsigned kfoff = ((warp * 16 + (lane & 15)) * 72 + (lane >> 4) * 8) * 2;
#pragma unroll 1
  for (int kt = 0; kt < 8; kt++) {
    if (kt < 7) load_k(kt + 1, (kt + 1) & 1);
    else        load_v(0, 0);           // stage0 free; overlaps softmax
    asm volatile("cp.async.wait_group 1;\n" ::: "memory");
    __syncthreads();
    const unsigned kb = kvbase + (kt & 1) * ATT_STG;
    unsigned kh[4][4], kl[4][4];
#pragma unroll
    for (int c = 0; c < 4; c++) {
      ldsm4(kh[c], kb + kfoff + c * 32);
      ldsm4(kl[c], kb + ATT_LO + kfoff + c * 32);
    }
    float a[2][2][4] = {};
#pragma unroll
    for (int c = 0; c < 4; c++)
#pragma unroll
      for (int i = 0; i < 2; i++) {
        mma16816(a[i][0], qh[i][c], kh[c][0], kh[c][2]);
        mma16816(a[i][0], qh[i][c], kl[c][0], kl[c][2]);
        mma16816(a[i][0], ql[i][c], kh[c][0], kh[c][2]);
        mma16816(a[i][1], qh[i][c], kh[c][1], kh[c][3]);
        mma16816(a[i][1], qh[i][c], kl[c][1], kl[c][3]);
        mma16816(a[i][1], ql[i][c], kh[c][1], kh[c][3]);
      }
    const int key0 = kt * 128 + warp * 16;
#pragma unroll
    for (int i = 0; i < 2; i++)
#pragma unroll
      for (int jj = 0; jj < 2; jj++) {
        const int col = key0 + jj * 8 + 2 * tg;
        *reinterpret_cast<float2*>(&S[(i * 16 + g) * SROW + col]) =
            make_float2(a[i][jj][0], a[i][jj][1]);
        *reinterpret_cast<float2*>(&S[(i * 16 + g + 8) * SROW + col]) =
            make_float2(a[i][jj][2], a[i][jj][3]);
      }
    __syncthreads();
  }

  // --- phase 2: exact softmax, write P packed (hi | lo<<16) in place ---
  {
    const int r = tid >> 3, ml = tid & 7;
    float* row = S + r * SROW;
    float mx = -1e30f;
    for (int k = ml * 4; k < N_; k += 32) {
      float4 v = *reinterpret_cast<float4*>(&row[k]);
      mx = fmaxf(mx, fmaxf(fmaxf(v.x, v.y), fmaxf(v.z, v.w)));
    }
#pragma unroll
    for (int o = 1; o < 8; o <<= 1) mx = fmaxf(mx, __shfl_xor_sync(0xffffffffu, mx, o));
    float s = 0.f;
    for (int k = ml * 4; k < N_; k += 32) {
      float4 v = *reinterpret_cast<float4*>(&row[k]);
      v.x = __expf(v.x - mx); v.y = __expf(v.y - mx);
      v.z = __expf(v.z - mx); v.w = __expf(v.w - mx);
      s += v.x + v.y + v.z + v.w;
      *reinterpret_cast<float4*>(&row[k]) = v;
    }
#pragma unroll
    for (int o = 1; o < 8; o <<= 1) s += __shfl_xor_sync(0xffffffffu, s, o);
    const float inv = 1.f / s;
    unsigned* urow = reinterpret_cast<unsigned*>(row);
    for (int k = ml * 4; k < N_; k += 32) {
      float4 v = *reinterpret_cast<float4*>(&row[k]);
      float p[4] = {v.x * inv, v.y * inv, v.z * inv, v.w * inv};
      unsigned u[4];
#pragma unroll
      for (int t = 0; t < 4; t++) {
        unsigned short h, l;
        splitf(p[t], h, l);
        u[t] = (unsigned)h | ((unsigned)l << 16);
      }
      urow[k] = u[0]; urow[k + 1] = u[1]; urow[k + 2] = u[2]; urow[k + 3] = u[3];
    }
  }
  __syncthreads();

  // --- phase 3: O = P V  (warp covers 8 head-dims; V^T tiles staged) ---
  const int n0 = warp * 8;
  const unsigned vfoff = ((n0 + (lane & 7)) * 136 + (lane >> 3) * 8) * 2;
  float oacc[2][4] = {};
#pragma unroll 1
  for (int vt = 0; vt < 8; vt++) {
    if (vt + 1 < 8) {
      load_v(vt + 1, (vt + 1) & 1);
      asm volatile("cp.async.wait_group 1;\n" ::: "memory");
    } else {
      asm volatile("cp.async.wait_group 0;\n" ::: "memory");
    }
    __syncthreads();
    const unsigned vb = kvbase + (vt & 1) * ATT_STG;
#pragma unroll
    for (int tt = 0; tt < 4; tt++) {
      unsigned vh[4], vl[4];
      ldsm4(vh, vb + vfoff + tt * 64);
      ldsm4(vl, vb + ATT_LO + vfoff + tt * 64);
#pragma unroll
      for (int sub = 0; sub < 2; sub++) {
        const int k0 = vt * 128 + (tt * 2 + sub) * 16;
#pragma unroll
        for (int i = 0; i < 2; i++) {
          const unsigned* p0 = &Sp[(size_t)(i * 16 + g) * SROW + k0 + 2 * tg];
          const unsigned* p8 = &Sp[(size_t)(i * 16 + g + 8) * SROW + k0 + 2 * tg];
          const uint2 s00 = *reinterpret_cast<const uint2*>(p0);
          const uint2 s08 = *reinterpret_cast<const uint2*>(p0 + 8);
          const uint2 s80 = *reinterpret_cast<const uint2*>(p8);
          const uint2 s88 = *reinterpret_cast<const uint2*>(p8 + 8);
          unsigned Ahf[4] = {__byte_perm(s00.x, s00.y, 0x5410),
                             __byte_perm(s80.x, s80.y, 0x5410),
                             __byte_perm(s08.x, s08.y, 0x5410),
                             __byte_perm(s88.x, s88.y, 0x5410)};
          unsigned Alf[4] = {__byte_perm(s00.x, s00.y, 0x7632),
                             __byte_perm(s80.x, s80.y, 0x7632),
                             __byte_perm(s08.x, s08.y, 0x7632),
                             __byte_perm(s88.x, s88.y, 0x7632)};
          mma16816(oacc[i], Ahf, vh[sub * 2], vh[sub * 2 + 1]);
          mma16816(oacc[i], Ahf, vl[sub * 2], vl[sub * 2 + 1]);
          mma16816(oacc[i], Alf, vh[sub * 2], vh[sub * 2 + 1]);
        }
      }
    }
    __syncthreads();
  }

  // --- write O as split bf16 (input to GEMM2) ---
  const int b = bh / H_, h = bh - (bh / H_) * H_;
#pragma unroll
  for (int i = 0; i < 2; i++) {
    const int row0 = b * N_ + q0 + i * 16 + g;
    const size_t o0 = (size_t)row0 * D_ + h * HD_ + n0 + 2 * tg;
    unsigned short h0, l0, h1, l1;
    splitf(oacc[i][0], h0, l0); splitf(oacc[i][1], h1, l1);
    *reinterpret_cast<unsigned*>(&g_Ah[o0]) = (unsigned)h0 | ((unsigned)h1 << 16);
    *reinterpret_cast<unsigned*>(&g_Al[o0]) = (unsigned)l0 | ((unsigned)l1 << 16);
    splitf(oacc[i][2], h0, l0); splitf(oacc[i][3], h1, l1);
    *reinterpret_cast<unsigned*>(&g_Ah[o0 + (size_t)8 * D_]) = (unsigned)h0 | ((unsigned)h1 << 16);
    *reinterpret_cast<unsigned*>(&g_Al[o0 + (size_t)8 * D_]) = (unsigned)l0 | ((unsigned)l1 << 16);
  }
}

// ---------------------------------------------------------------------------
extern "C" void kernel_launch(void* const* d_in, const int* in_sizes, int n_in,
                              void* d_out, int out_size)
{
  const float* x      = (const float*)d_in[0];
  const float* weight = (const float*)d_in[1];
  const float* W_qkv  = (const float*)d_in[2];
  const float* W_msa  = (const float*)d_in[3];
  const float* b_msa  = (const float*)d_in[4];
  float* out = (float*)d_out;

  unsigned short *xh, *xl, *wqh, *wql, *wmh, *wml, *ah, *al;
  cudaGetSymbolAddress((void**)&xh,  g_Xh);  cudaGetSymbolAddress((void**)&xl,  g_Xl);
  cudaGetSymbolAddress((void**)&wqh, g_Wqh); cudaGetSymbolAddress((void**)&wql, g_Wql);
  cudaGetSymbolAddress((void**)&wmh, g_Wmh); cudaGetSymbolAddress((void**)&wml, g_Wml);
  cudaGetSymbolAddress((void**)&ah,  g_Ah);  cudaGetSymbolAddress((void**)&al,  g_Al);

  cudaFuncSetAttribute(gemm_mma<D3_, 0>,
                       cudaFuncAttributeMaxDynamicSharedMemorySize, GEMM_SMEM);
  cudaFuncSetAttribute(gemm_mma<D_, 1>,
                       cudaFuncAttributeMaxDynamicSharedMemorySize, GEMM_SMEM);
  cudaFuncSetAttribute(attn_mma,
                       cudaFuncAttributeMaxDynamicSharedMemorySize, ATT_SMEM);

  // 0) pre-split fp32 -> hi/lo bf16
  split4<<<ROWS * D_ / 4 / 256, 256>>>((const float4*)x, (uint2*)xh, (uint2*)xl,
                                       ROWS * D_ / 4);
  split4<<<D_ * D3_ / 4 / 256, 256>>>((const float4*)W_qkv, (uint2*)wqh, (uint2*)wql,
                                      D_ * D3_ / 4);
  split4<<<D_ * D_ / 4 / 256, 256>>>((const float4*)W_msa, (uint2*)wmh, (uint2*)wml,
                                     D_ * D_ / 4);
  // 1) QKV projection + gate + head-major scatter
  gemm_mma<D3_, 0><<<dim3(D3_ / 128, ROWS / 128), 256, GEMM_SMEM>>>(
      xh, xl, wqh, wql, weight, nullptr);
  // 2) attention
  attn_mma<<<dim3(N_ / 32, NBH), 256, ATT_SMEM>>>();
  // 3) output projection + bias
  gemm_mma<D_, 1><<<dim3(D_ / 128, ROWS / 128), 256, GEMM_SMEM>>>(
      ah, al, wmh, wml, b_msa, out);
}

// round 9
// speedup vs baseline: 3.7108x; 1.3436x over previous
#include <cuda_runtime.h>
#include <cuda_bf16.h>

#define B_   8
#define N_   1024
#define D_   768
#define H_   12
#define HD_  64
#define ROWS (B_ * N_)      // 8192
#define D3_  (3 * D_)       // 2304
#define SCALE_ 0.125f
#define NBH  (B_ * H_)      // 96

// ---------------- split bf16 scratch (alloc-free rule: device globals) -----
__device__ __align__(16) unsigned short g_Xh[ROWS * D_];
__device__ __align__(16) unsigned short g_Xl[ROWS * D_];
__device__ __align__(16) unsigned short g_Wqh[D_ * D3_];
__device__ __align__(16) unsigned short g_Wql[D_ * D3_];
__device__ __align__(16) unsigned short g_Wmh[D_ * D_];
__device__ __align__(16) unsigned short g_Wml[D_ * D_];
__device__ __align__(16) unsigned short g_Qh[NBH * N_ * HD_];
__device__ __align__(16) unsigned short g_Ql[NBH * N_ * HD_];
__device__ __align__(16) unsigned short g_Kh[NBH * N_ * HD_];
__device__ __align__(16) unsigned short g_Kl[NBH * N_ * HD_];
__device__ __align__(16) unsigned short g_Vth[NBH * HD_ * N_];  // [bh][hd][key]
__device__ __align__(16) unsigned short g_Vtl[NBH * HD_ * N_];
__device__ __align__(16) unsigned short g_Ah[ROWS * D_];        // attn out hi
__device__ __align__(16) unsigned short g_Al[ROWS * D_];        // attn out lo

// ---------------- helpers --------------------------------------------------
__device__ __forceinline__ unsigned short bf16_rn(float x) {
  unsigned u = __float_as_uint(x);
  return (unsigned short)((u + 0x7fffu + ((u >> 16) & 1u)) >> 16);
}
__device__ __forceinline__ float bf16_tof(unsigned short h) {
  return __uint_as_float(((unsigned)h) << 16);
}
__device__ __forceinline__ void splitf(float x, unsigned short& h, unsigned short& l) {
  h = bf16_rn(x);
  l = bf16_rn(x - bf16_tof(h));
}
__device__ __forceinline__ unsigned packsplit(float x) {   // hi | lo<<16
  unsigned short h, l;
  splitf(x, h, l);
  return (unsigned)h | ((unsigned)l << 16);
}
__device__ __forceinline__ void mma16816(float* c, const unsigned* a,
                                         unsigned b0, unsigned b1) {
  asm volatile(
      "mma.sync.aligned.m16n8k16.row.col.f32.bf16.bf16.f32 "
      "{%0,%1,%2,%3}, {%4,%5,%6,%7}, {%8,%9}, {%0,%1,%2,%3};\n"
      : "+f"(c[0]), "+f"(c[1]), "+f"(c[2]), "+f"(c[3])
      : "r"(a[0]), "r"(a[1]), "r"(a[2]), "r"(a[3]), "r"(b0), "r"(b1));
}
__device__ __forceinline__ void ldsm4(unsigned* r, unsigned a) {
  asm volatile("ldmatrix.sync.aligned.m8n8.x4.shared.b16 {%0,%1,%2,%3}, [%4];\n"
               : "=r"(r[0]), "=r"(r[1]), "=r"(r[2]), "=r"(r[3]) : "r"(a));
}
__device__ __forceinline__ void ldsm4t(unsigned* r, unsigned a) {
  asm volatile("ldmatrix.sync.aligned.m8n8.x4.trans.shared.b16 {%0,%1,%2,%3}, [%4];\n"
               : "=r"(r[0]), "=r"(r[1]), "=r"(r[2]), "=r"(r[3]) : "r"(a));
}
__device__ __forceinline__ void cp16(void* smem, const void* gmem) {
  unsigned s = (unsigned)__cvta_generic_to_shared(smem);
  asm volatile("cp.async.cg.shared.global [%0], [%1], 16;\n" :: "r"(s), "l"(gmem));
}

// ---------------- pre-split: fp32 -> hi/lo bf16 ----------------------------
__global__ void split4(const float4* __restrict__ src, uint2* __restrict__ dh,
                       uint2* __restrict__ dl, int n4) {
  int i = blockIdx.x * blockDim.x + threadIdx.x;
  if (i >= n4) return;
  float4 v = src[i];
  unsigned short h0, l0, h1, l1, h2, l2, h3, l3;
  splitf(v.x, h0, l0); splitf(v.y, h1, l1);
  splitf(v.z, h2, l2); splitf(v.w, h3, l3);
  dh[i] = make_uint2((unsigned)h0 | ((unsigned)h1 << 16),
                     (unsigned)h2 | ((unsigned)h3 << 16));
  dl[i] = make_uint2((unsigned)l0 | ((unsigned)l1 << 16),
                     (unsigned)l2 | ((unsigned)l3 << 16));
}

// ---------------------------------------------------------------------------
// Split-bf16 GEMM with cp.async double-buffer + ldmatrix. (unchanged from R5)
// ---------------------------------------------------------------------------
#define GEMM_SMEM 75776

template <int LDB, int MODE>
__global__ __launch_bounds__(256) void gemm_mma(
    const unsigned short* __restrict__ Agh, const unsigned short* __restrict__ Agl,
    const unsigned short* __restrict__ Bgh, const unsigned short* __restrict__ Bgl,
    const float* __restrict__ aux, float* __restrict__ C)
{
  extern __shared__ __align__(16) unsigned short smem_u16[];
  const int tid = threadIdx.x, lane = tid & 31, warp = tid >> 5;
  const int g = lane >> 2, tg = lane & 3;
  const int wm = (warp >> 2) * 64, wn = (warp & 3) * 32;
  const int bx = blockIdx.x, by = blockIdx.y;

  float acc[4][4][4] = {};

  const unsigned sbase = (unsigned)__cvta_generic_to_shared(smem_u16);
  const unsigned aoff = ((wm + (lane & 15)) * 40 + (lane >> 4) * 8) * 2;
  const unsigned boff = ((lane & 15) * 136 + wn + (lane >> 4) * 8) * 2;

  auto load_stage = [&](int k0, int st) {
    unsigned short* dAh = smem_u16 + st * 5120;
    unsigned short* dAl = smem_u16 + 10240 + st * 5120;
    unsigned short* dBh = smem_u16 + 20480 + st * 4352;
    unsigned short* dBl = smem_u16 + 29184 + st * 4352;
#pragma unroll
    for (int t = 0; t < 2; t++) {
      int c = tid + t * 256;
      int ar = c >> 2, ak = (c & 3) * 8;
      size_t ga = (size_t)(by * 128 + ar) * D_ + k0 + ak;
      cp16(dAh + ar * 40 + ak, Agh + ga);
      cp16(dAl + ar * 40 + ak, Agl + ga);
      int br = c >> 4, bn = (c & 15) * 8;
      size_t gb = (size_t)(k0 + br) * LDB + bx * 128 + bn;
      cp16(dBh + br * 136 + bn, Bgh + gb);
      cp16(dBl + br * 136 + bn, Bgl + gb);
    }
    asm volatile("cp.async.commit_group;\n" ::: "memory");
  };

  load_stage(0, 0);
  for (int it = 0; it < 24; it++) {
    if (it + 1 < 24) {
      load_stage((it + 1) * 32, (it + 1) & 1);
      asm volatile("cp.async.wait_group 1;\n" ::: "memory");
    } else {
      asm volatile("cp.async.wait_group 0;\n" ::: "memory");
    }
    __syncthreads();
    const int st = it & 1;
    const unsigned sAh = sbase + st * 10240;
    const unsigned sAl = sbase + 20480 + st * 10240;
    const unsigned sBh = sbase + 40960 + st * 8704;
    const unsigned sBl = sbase + 58368 + st * 8704;
#pragma unroll
    for (int kk = 0; kk < 2; kk++) {
      unsigned ah[4][4], al[4][4], bh[2][4], bl[2][4];
#pragma unroll
      for (int i = 0; i < 4; i++) {
        ldsm4(ah[i], sAh + aoff + i * 1280 + kk * 32);
        ldsm4(al[i], sAl + aoff + i * 1280 + kk * 32);
      }
#pragma unroll
      for (int jj = 0; jj < 2; jj++) {
        ldsm4t(bh[jj], sBh + boff + kk * 4352 + jj * 32);
        ldsm4t(bl[jj], sBl + boff + kk * 4352 + jj * 32);
      }
#pragma unroll
      for (int i = 0; i < 4; i++)
#pragma unroll
        for (int jj = 0; jj < 2; jj++) {
          mma16816(acc[i][2 * jj], ah[i], bh[jj][0], bh[jj][1]);
          mma16816(acc[i][2 * jj], ah[i], bl[jj][0], bl[jj][1]);
          mma16816(acc[i][2 * jj], al[i], bh[jj][0], bh[jj][1]);
          mma16816(acc[i][2 * jj + 1], ah[i], bh[jj][2], bh[jj][3]);
          mma16816(acc[i][2 * jj + 1], ah[i], bl[jj][2], bl[jj][3]);
          mma16816(acc[i][2 * jj + 1], al[i], bh[jj][2], bh[jj][3]);
        }
    }
    __syncthreads();
  }

  if constexpr (MODE == 0) {
    const int which = bx / 6;   // 0=Q 1=K 2=V
#pragma unroll
    for (int i = 0; i < 4; i++) {
#pragma unroll
      for (int half = 0; half < 2; half++) {
        const int m = by * 128 + wm + i * 16 + g + half * 8;
        const float gate = aux[m];
        const int b = m >> 10, tok = m & 1023;
#pragma unroll
        for (int j = 0; j < 4; j++) {
          const int col = bx * 128 + wn + j * 8 + 2 * tg;
          const int dd = col - which * D_;
          const int h = dd >> 6, hd = dd & 63;
          const int bh = b * H_ + h;
          float v0 = acc[i][j][half * 2 + 0] * gate;
          float v1 = acc[i][j][half * 2 + 1] * gate;
          if (which == 0) { v0 *= SCALE_; v1 *= SCALE_; }
          unsigned short h0, l0, h1, l1;
          splitf(v0, h0, l0); splitf(v1, h1, l1);
          if (which == 0) {
            const size_t idx = ((size_t)bh * N_ + tok) * HD_ + hd;
            *reinterpret_cast<unsigned*>(&g_Qh[idx]) = (unsigned)h0 | ((unsigned)h1 << 16);
            *reinterpret_cast<unsigned*>(&g_Ql[idx]) = (unsigned)l0 | ((unsigned)l1 << 16);
          } else if (which == 1) {
            const size_t idx = ((size_t)bh * N_ + tok) * HD_ + hd;
            *reinterpret_cast<unsigned*>(&g_Kh[idx]) = (unsigned)h0 | ((unsigned)h1 << 16);
            *reinterpret_cast<unsigned*>(&g_Kl[idx]) = (unsigned)l0 | ((unsigned)l1 << 16);
          } else {
            const size_t r0 = ((size_t)bh * HD_ + hd) * N_ + tok;
            g_Vth[r0] = h0; g_Vth[r0 + N_] = h1;
            g_Vtl[r0] = l0; g_Vtl[r0 + N_] = l1;
          }
        }
      }
    }
  } else {
#pragma unroll
    for (int i = 0; i < 4; i++)
#pragma unroll
      for (int half = 0; half < 2; half++) {
        const int m = by * 128 + wm + i * 16 + g + half * 8;
#pragma unroll
        for (int j = 0; j < 4; j++) {
          const int col = bx * 128 + wn + j * 8 + 2 * tg;
          float2 o;
          o.x = acc[i][j][half * 2 + 0] + aux[col];
          o.y = acc[i][j][half * 2 + 1] + aux[col + 1];
          *reinterpret_cast<float2*>(&C[(size_t)m * D_ + col]) = o;
        }
      }
  }
}

// ---------------------------------------------------------------------------
// Flash attention: 128 queries/CTA (8 warps x m16), online softmax, S and P
// entirely in registers. K tile -> buf0, V^T tile -> buf1 (cp.async ping-pong).
// SMEM: 2 x 36,864 B = 73,728 B.
// ---------------------------------------------------------------------------
#define FA_STG  36864    // bytes per buffer
#define FA_LO   18432    // byte offset of lo plane within a buffer
#define FA_SMEM (2 * FA_STG)

__global__ __launch_bounds__(256, 1) void attn_flash()
{
  extern __shared__ __align__(16) unsigned short KV[];
  const unsigned kvb = (unsigned)__cvta_generic_to_shared(KV);

  const int tid = threadIdx.x, lane = tid & 31, warp = tid >> 5;
  const int g = lane >> 2, tg = lane & 3;
  const int bh = blockIdx.y;
  const int q0 = blockIdx.x * 128;
  const size_t kbase = (size_t)bh * N_ * HD_;
  const size_t vbase = (size_t)bh * HD_ * N_;
  const size_t qrow = kbase + (size_t)(q0 + warp * 16 + g) * HD_;

  auto load_k = [&](int kt) {
    unsigned short* dst = KV;                       // buf0
    const unsigned short* sh = g_Kh + kbase + (size_t)kt * 128 * HD_;
    const unsigned short* sl = g_Kl + kbase + (size_t)kt * 128 * HD_;
#pragma unroll
    for (int t = 0; t < 4; t++) {
      int c = tid + t * 256;
      int row = c >> 3, ko = (c & 7) * 8;
      cp16(dst + row * 72 + ko, sh + row * HD_ + ko);
      cp16(dst + 9216 + row * 72 + ko, sl + row * HD_ + ko);
    }
    asm volatile("cp.async.commit_group;\n" ::: "memory");
  };
  auto load_v = [&](int vt) {
    unsigned short* dst = KV + 18432;               // buf1
    const unsigned short* sh = g_Vth + vbase + vt * 128;
    const unsigned short* sl = g_Vtl + vbase + vt * 128;
#pragma unroll
    for (int t = 0; t < 4; t++) {
      int c = tid + t * 256;
      int row = c >> 4, no = (c & 15) * 8;
      cp16(dst + row * 136 + no, sh + (size_t)row * N_ + no);
      cp16(dst + 9216 + row * 136 + no, sl + (size_t)row * N_ + no);
    }
    asm volatile("cp.async.commit_group;\n" ::: "memory");
  };

  load_k(0);
  load_v(0);

  // --- resident Q fragments: 1 m16 tile x 4 k16 chunks, hi + lo ---
  unsigned qh[4][4], ql[4][4];
#pragma unroll
  for (int c = 0; c < 4; c++) {
    const size_t r0 = qrow + c * 16 + 2 * tg;
    const size_t r8 = r0 + 8 * HD_;
    qh[c][0] = *reinterpret_cast<const unsigned*>(&g_Qh[r0]);
    qh[c][1] = *reinterpret_cast<const unsigned*>(&g_Qh[r8]);
    qh[c][2] = *reinterpret_cast<const unsigned*>(&g_Qh[r0 + 8]);
    qh[c][3] = *reinterpret_cast<const unsigned*>(&g_Qh[r8 + 8]);
    ql[c][0] = *reinterpret_cast<const unsigned*>(&g_Ql[r0]);
    ql[c][1] = *reinterpret_cast<const unsigned*>(&g_Ql[r8]);
    ql[c][2] = *reinterpret_cast<const unsigned*>(&g_Ql[r0 + 8]);
    ql[c][3] = *reinterpret_cast<const unsigned*>(&g_Ql[r8 + 8]);
  }

  float oacc[8][4] = {};
  float m0 = -1e30f, m1 = -1e30f, l0 = 0.f, l1 = 0.f;

  const unsigned kfb = ((lane & 15) * 72 + (lane >> 4) * 8) * 2;   // K frag base
  const unsigned vfb = ((lane & 7) * 136 + (lane >> 3) * 8) * 2;   // V frag base

#pragma unroll 1
  for (int kt = 0; kt < 8; kt++) {
    // ---- S = Q K^T over this 128-key tile (registers only) ----
    asm volatile("cp.async.wait_group 1;\n" ::: "memory");   // K tile ready
    __syncthreads();
    float sacc[16][4] = {};
#pragma unroll
    for (int kg = 0; kg < 8; kg++) {
      const unsigned kb = kvb + kg * 2304 + kfb;
      unsigned kh[4][4], kl[4][4];
#pragma unroll
      for (int c = 0; c < 4; c++) {
        ldsm4(kh[c], kb + c * 32);
        ldsm4(kl[c], kb + FA_LO + c * 32);
      }
#pragma unroll
      for (int c = 0; c < 4; c++) {
        mma16816(sacc[2 * kg],     qh[c], kh[c][0], kh[c][2]);
        mma16816(sacc[2 * kg],     qh[c], kl[c][0], kl[c][2]);
        mma16816(sacc[2 * kg],     ql[c], kh[c][0], kh[c][2]);
        mma16816(sacc[2 * kg + 1], qh[c], kh[c][1], kh[c][3]);
        mma16816(sacc[2 * kg + 1], qh[c], kl[c][1], kl[c][3]);
        mma16816(sacc[2 * kg + 1], ql[c], kh[c][1], kh[c][3]);
      }
    }
    __syncthreads();                 // done reading buf0
    if (kt < 7) load_k(kt + 1);      // prefetch next K (overlaps softmax)

    // ---- online softmax (rows g and g+8; quad shuffles over tg) ----
    float mx0 = -1e30f, mx1 = -1e30f;
#pragma unroll
    for (int t = 0; t < 16; t++) {
      mx0 = fmaxf(mx0, fmaxf(sacc[t][0], sacc[t][1]));
      mx1 = fmaxf(mx1, fmaxf(sacc[t][2], sacc[t][3]));
    }
    mx0 = fmaxf(mx0, __shfl_xor_sync(0xffffffffu, mx0, 1));
    mx0 = fmaxf(mx0, __shfl_xor_sync(0xffffffffu, mx0, 2));
    mx1 = fmaxf(mx1, __shfl_xor_sync(0xffffffffu, mx1, 1));
    mx1 = fmaxf(mx1, __shfl_xor_sync(0xffffffffu, mx1, 2));
    const float m0n = fmaxf(m0, mx0), m1n = fmaxf(m1, mx1);
    const float c0 = __expf(m0 - m0n), c1 = __expf(m1 - m1n);
    m0 = m0n; m1 = m1n;
    float ts0 = 0.f, ts1 = 0.f;
#pragma unroll
    for (int t = 0; t < 16; t++) {
      float p0 = __expf(sacc[t][0] - m0n), p1 = __expf(sacc[t][1] - m0n);
      float p2 = __expf(sacc[t][2] - m1n), p3 = __expf(sacc[t][3] - m1n);
      ts0 += p0 + p1; ts1 += p2 + p3;
      sacc[t][0] = __uint_as_float(packsplit(p0));
      sacc[t][1] = __uint_as_float(packsplit(p1));
      sacc[t][2] = __uint_as_float(packsplit(p2));
      sacc[t][3] = __uint_as_float(packsplit(p3));
    }
    ts0 += __shfl_xor_sync(0xffffffffu, ts0, 1);
    ts0 += __shfl_xor_sync(0xffffffffu, ts0, 2);
    ts1 += __shfl_xor_sync(0xffffffffu, ts1, 1);
    ts1 += __shfl_xor_sync(0xffffffffu, ts1, 2);
    l0 = l0 * c0 + ts0;
    l1 = l1 * c1 + ts1;
#pragma unroll
    for (int vn = 0; vn < 8; vn++) {
      oacc[vn][0] *= c0; oacc[vn][1] *= c0;
      oacc[vn][2] *= c1; oacc[vn][3] *= c1;
    }

    // ---- O += P V over this tile ----
    asm volatile("cp.async.wait_group %0;\n" :: "n"(1) : "memory");  // V (K' in flight)
    if (kt == 7) asm volatile("cp.async.wait_group 0;\n" ::: "memory");
    __syncthreads();
#pragma unroll
    for (int tt = 0; tt < 4; tt++) {
      // build split-P A-fragments for k-chunks 2tt, 2tt+1 from packed sacc
      unsigned pfh[2][4], pfl[2][4];
#pragma unroll
      for (int cc = 0; cc < 2; cc++) {
        const int t0 = (2 * tt + cc) * 2;
        const unsigned u0 = __float_as_uint(sacc[t0][0]);
        const unsigned u1 = __float_as_uint(sacc[t0][1]);
        const unsigned u2 = __float_as_uint(sacc[t0][2]);
        const unsigned u3 = __float_as_uint(sacc[t0][3]);
        const unsigned w0 = __float_as_uint(sacc[t0 + 1][0]);
        const unsigned w1 = __float_as_uint(sacc[t0 + 1][1]);
        const unsigned w2 = __float_as_uint(sacc[t0 + 1][2]);
        const unsigned w3 = __float_as_uint(sacc[t0 + 1][3]);
        pfh[cc][0] = __byte_perm(u0, u1, 0x5410);
        pfh[cc][1] = __byte_perm(u2, u3, 0x5410);
        pfh[cc][2] = __byte_perm(w0, w1, 0x5410);
        pfh[cc][3] = __byte_perm(w2, w3, 0x5410);
        pfl[cc][0] = __byte_perm(u0, u1, 0x7632);
        pfl[cc][1] = __byte_perm(u2, u3, 0x7632);
        pfl[cc][2] = __byte_perm(w0, w1, 0x7632);
        pfl[cc][3] = __byte_perm(w2, w3, 0x7632);
      }
#pragma unroll
      for (int vn = 0; vn < 8; vn++) {
        const unsigned vb = kvb + FA_STG + vn * 2176 + vfb + tt * 64;
        unsigned vh[4], vl[4];
        ldsm4(vh, vb);
        ldsm4(vl, vb + FA_LO);
        mma16816(oacc[vn], pfh[0], vh[0], vh[1]);
        mma16816(oacc[vn], pfh[0], vl[0], vl[1]);
        mma16816(oacc[vn], pfl[0], vh[0], vh[1]);
        mma16816(oacc[vn], pfh[1], vh[2], vh[3]);
        mma16816(oacc[vn], pfh[1], vl[2], vl[3]);
        mma16816(oacc[vn], pfl[1], vh[2], vh[3]);
      }
    }
    __syncthreads();                 // done reading buf1
    if (kt < 7) load_v(kt + 1);      // prefetch next V
  }

  // ---- finalize: normalize, write split bf16 O for GEMM2 ----
  const float inv0 = 1.f / l0, inv1 = 1.f / l1;
  const int b = bh / H_, h = bh - (bh / H_) * H_;
  const int tok = q0 + warp * 16 + g;
  const size_t base0 = (size_t)(b * N_ + tok) * D_ + h * HD_ + 2 * tg;
  const size_t base8 = base0 + (size_t)8 * D_;
#pragma unroll
  for (int vn = 0; vn < 8; vn++) {
    unsigned short h0, l0s, h1, l1s;
    splitf(oacc[vn][0] * inv0, h0, l0s); splitf(oacc[vn][1] * inv0, h1, l1s);
    *reinterpret_cast<unsigned*>(&g_Ah[base0 + vn * 8]) = (unsigned)h0 | ((unsigned)h1 << 16);
    *reinterpret_cast<unsigned*>(&g_Al[base0 + vn * 8]) = (unsigned)l0s | ((unsigned)l1s << 16);
    splitf(oacc[vn][2] * inv1, h0, l0s); splitf(oacc[vn][3] * inv1, h1, l1s);
    *reinterpret_cast<unsigned*>(&g_Ah[base8 + vn * 8]) = (unsigned)h0 | ((unsigned)h1 << 16);
    *reinterpret_cast<unsigned*>(&g_Al[base8 + vn * 8]) = (unsigned)l0s | ((unsigned)l1s << 16);
  }
}

// ---------------------------------------------------------------------------
extern "C" void kernel_launch(void* const* d_in, const int* in_sizes, int n_in,
                              void* d_out, int out_size)
{
  const float* x      = (const float*)d_in[0];
  const float* weight = (const float*)d_in[1];
  const float* W_qkv  = (const float*)d_in[2];
  const float* W_msa  = (const float*)d_in[3];
  const float* b_msa  = (const float*)d_in[4];
  float* out = (float*)d_out;

  unsigned short *xh, *xl, *wqh, *wql, *wmh, *wml, *ah, *al;
  cudaGetSymbolAddress((void**)&xh,  g_Xh);  cudaGetSymbolAddress((void**)&xl,  g_Xl);
  cudaGetSymbolAddress((void**)&wqh, g_Wqh); cudaGetSymbolAddress((void**)&wql, g_Wql);
  cudaGetSymbolAddress((void**)&wmh, g_Wmh); cudaGetSymbolAddress((void**)&wml, g_Wml);
  cudaGetSymbolAddress((void**)&ah,  g_Ah);  cudaGetSymbolAddress((void**)&al,  g_Al);

  cudaFuncSetAttribute(gemm_mma<D3_, 0>,
                       cudaFuncAttributeMaxDynamicSharedMemorySize, GEMM_SMEM);
  cudaFuncSetAttribute(gemm_mma<D_, 1>,
                       cudaFuncAttributeMaxDynamicSharedMemorySize, GEMM_SMEM);
  cudaFuncSetAttribute(attn_flash,
                       cudaFuncAttributeMaxDynamicSharedMemorySize, FA_SMEM);

  split4<<<ROWS * D_ / 4 / 256, 256>>>((const float4*)x, (uint2*)xh, (uint2*)xl,
                                       ROWS * D_ / 4);
  split4<<<D_ * D3_ / 4 / 256, 256>>>((const float4*)W_qkv, (uint2*)wqh, (uint2*)wql,
                                      D_ * D3_ / 4);
  split4<<<D_ * D_ / 4 / 256, 256>>>((const float4*)W_msa, (uint2*)wmh, (uint2*)wml,
                                     D_ * D_ / 4);
  gemm_mma<D3_, 0><<<dim3(D3_ / 128, ROWS / 128), 256, GEMM_SMEM>>>(
      xh, xl, wqh, wql, weight, nullptr);
  attn_flash<<<dim3(N_ / 128, NBH), 256, FA_SMEM>>>();
  gemm_mma<D_, 1><<<dim3(D_ / 128, ROWS / 128), 256, GEMM_SMEM>>>(
      ah, al, wmh, wml, b_msa, out);
}